// round 12
// baseline (speedup 1.0000x reference)
#include <cuda_runtime.h>
#include <cstdint>

typedef unsigned long long ull;

#define MAX_NTOK 32768
#define GE 160
#define WSIZE (160*160)
#define TOKB 64
#define NV 128            // GE-vectors per block (2 per token)
#define HSS 160           // H row stride (floats), even -> 8B aligned rows
#define WS  162           // transposed-W row stride (floats), even for LDS.64
#define SMEM_FLOATS (GE*WS + NV*HSS + GE)
#define SMEM_BYTES  (SMEM_FLOATS*4)      // 186 368 B

__device__ int   g_count;
__device__ int   g_tok[MAX_NTOK];
__device__ int   g_nib[MAX_NTOK];
__device__ float g_op [MAX_NTOK];

// ---- packed fp32x2 helpers (Blackwell FFMA2 path) ----
__device__ __forceinline__ void ffma2(ull& d, ull a, ull b) {
    asm("fma.rn.f32x2 %0, %1, %2, %0;" : "+l"(d) : "l"(a), "l"(b));
}
__device__ __forceinline__ ull pack2(float x) {
    ull r;
    asm("mov.b64 %0, {%1, %1};" : "=l"(r) : "f"(x));
    return r;
}

// first index k in [0,16) of the 16-float window whose value > 0.5, else 0.
__device__ __forceinline__ int first_set_idx(unsigned b0, unsigned b1,
                                             unsigned b2, unsigned b3, int sh) {
    int best = 100;
    unsigned m;
    m = (b0 >> sh) & 0xFu; if (m) { int c = 4*(__ffs(m)-1) + 0; if (c < best) best = c; }
    m = (b1 >> sh) & 0xFu; if (m) { int c = 4*(__ffs(m)-1) + 1; if (c < best) best = c; }
    m = (b2 >> sh) & 0xFu; if (m) { int c = 4*(__ffs(m)-1) + 2; if (c < best) best = c; }
    m = (b3 >> sh) & 0xFu; if (m) { int c = 4*(__ffs(m)-1) + 3; if (c < best) best = c; }
    return (best >= 100) ? 0 : best;
}

// One warp per token: float4 copy in->out; decode gates/nibbles/opcode from the
// already-loaded registers via ballots; append active tokens to compaction list.
__global__ void __launch_bounds__(256)
copy_detect_kernel(const float* __restrict__ x, float* __restrict__ out, int ntok) {
    int tok  = blockIdx.x * 8 + (threadIdx.x >> 5);
    int lane = threadIdx.x & 31;
    if (tok >= ntok) return;

    const float4* src = reinterpret_cast<const float4*>(x) + (size_t)tok * 128;
    float4*       dst = reinterpret_cast<float4*>(out)      + (size_t)tok * 128;

    float4 v0 = src[lane];
    float4 v1 = src[lane + 32];
    float4 v2 = src[lane + 64];
    float4 v3 = src[lane + 96];
    dst[lane]      = v0;
    dst[lane + 32] = v1;
    dst[lane + 64] = v2;
    dst[lane + 96] = v3;

    unsigned b0 = __ballot_sync(0xffffffffu, v0.x > 0.5f);
    unsigned b1 = __ballot_sync(0xffffffffu, v0.y > 0.5f);
    unsigned b2 = __ballot_sync(0xffffffffu, v0.z > 0.5f);
    unsigned b3 = __ballot_sync(0xffffffffu, v0.w > 0.5f);

    float op = __shfl_sync(0xffffffffu, v0.y, 7);   // float 29 = OPCODE_BASE+27

    if (lane == 0 && v0.x >= 0.5f && v0.y >= 0.5f) {
        int a_lo = first_set_idx(b0, b1, b2, b3, 16);
        int a_hi = first_set_idx(b0, b1, b2, b3, 20);
        int b_lo = first_set_idx(b0, b1, b2, b3, 24);
        int b_hi = first_set_idx(b0, b1, b2, b3, 28);
        int idx = atomicAdd(&g_count, 1);
        g_tok[idx] = tok;
        g_nib[idx] = a_lo | (a_hi << 8) | (b_lo << 16) | (b_hi << 24);
        g_op[idx]  = op;
    }
}

// 64 active tokens (128 GE-vectors) per block, 512 threads (16 warps).
// Thread (vg,eg): vg=tid>>4 (half-warp) owns 4 vectors, eg=tid&15 owns 10 outputs.
// H rows half-warp-private -> single in-place H buffer, no intra-layer syncs.
__global__ void __launch_bounds__(512, 1)
mlp_kernel(const float* __restrict__ W, const float* __restrict__ bias,
           float* __restrict__ out) {
    extern __shared__ float smf[];
    float* WT = smf;                  // [160][WS] transposed layer weights
    float* H  = smf + GE * WS;        // [NV][HSS]
    float* w6 = H + NV * HSS;         // [160]
    __shared__ float sA[NV], sBn[NV], sOp[NV];
    __shared__ int   sTok[TOKB];

    int count = g_count;
    int t0 = blockIdx.x * TOKB;
    if (t0 >= count) return;
    int tid = threadIdx.x;

    // ---- prologue: token metadata, stage WT(layer1) and w6 ----
    if (tid < TOKB) {
        int gi = t0 + tid;
        if (gi < count) {
            int   nib = g_nib[gi];
            float op  = g_op[gi];
            sTok[tid]    = g_tok[gi];
            sA [2*tid]   = (float)( nib        & 0xFF);
            sA [2*tid+1] = (float)((nib >> 8)  & 0xFF);
            sBn[2*tid]   = (float)((nib >> 16) & 0xFF);
            sBn[2*tid+1] = (float)((nib >> 24) & 0xFF);
            sOp[2*tid]   = op;
            sOp[2*tid+1] = op;
        } else {
            sTok[tid] = -1;
            sA [2*tid] = 0.f; sA [2*tid+1] = 0.f;
            sBn[2*tid] = 0.f; sBn[2*tid+1] = 0.f;
            sOp[2*tid] = 0.f; sOp[2*tid+1] = 0.f;
        }
    }
    {
        const float4* Wl4 = reinterpret_cast<const float4*>(W + WSIZE);
        for (int idx = tid; idx < WSIZE / 4; idx += 512) {
            float4 v = Wl4[idx];
            int e = (idx * 4) / 160, d = (idx * 4) % 160;   // 4 consecutive d
            WT[(d+0)*WS + e] = v.x; WT[(d+1)*WS + e] = v.y;
            WT[(d+2)*WS + e] = v.z; WT[(d+3)*WS + e] = v.w;
        }
        if (tid < GE) w6[tid] = W[6*WSIZE + 2*GE + tid];
    }
    __syncthreads();

    int vg = tid >> 4, eg = tid & 15;   // vg: half-warp id (0..31)
    int vb = vg * 4,   eb = eg * 10;

    // ---- layer 0: input is 3-sparse (NIB_A@0, NIB_B@1, op@30) ----
    {
        float wc0[10], wc1[10], wc30[10], bb[10];
        #pragma unroll
        for (int k = 0; k < 10; ++k) {
            int e = eb + k;
            wc0[k]  = W[e*160 + 0];
            wc1[k]  = W[e*160 + 1];
            wc30[k] = W[e*160 + 30];
            bb[k]   = bias[e];
        }
        #pragma unroll
        for (int j = 0; j < 4; ++j) {
            int v = vb + j;
            float a = sA[v], bn = sBn[v], op = sOp[v];
            float* hrow = H + v * HSS;
            #pragma unroll
            for (int k = 0; k < 10; ++k) {
                float acc = bb[k];
                acc = fmaf(a,  wc0[k],  acc);
                acc = fmaf(bn, wc1[k],  acc);
                acc = fmaf(op, wc30[k], acc);
                hrow[eb + k] = fmaxf(acc, 0.f);
            }
        }
    }
    // H rows are half-warp private; same warp reads them next -> no sync needed.

    // ---- dense layers 1..5: FFMA2, d-unrolled x2, in-place H ----
    for (int layer = 1; layer <= 5; ++layer) {
        const float* bl = bias + layer * GE + eb;
        ull acc[4][5];
        #pragma unroll
        for (int k = 0; k < 5; ++k) {
            ull bv = *reinterpret_cast<const ull*>(bl + 2*k);
            acc[0][k] = bv; acc[1][k] = bv; acc[2][k] = bv; acc[3][k] = bv;
        }
        const float* hbase = H + vb * HSS;
        const float* wp = WT + eb;
        #pragma unroll 2
        for (int d = 0; d < GE; d += 2) {
            const float* wr0 = wp + d * WS;
            const float* wr1 = wr0 + WS;
            ull wA0 = *reinterpret_cast<const ull*>(wr0 + 0);
            ull wA1 = *reinterpret_cast<const ull*>(wr0 + 2);
            ull wA2 = *reinterpret_cast<const ull*>(wr0 + 4);
            ull wA3 = *reinterpret_cast<const ull*>(wr0 + 6);
            ull wA4 = *reinterpret_cast<const ull*>(wr0 + 8);
            ull wB0 = *reinterpret_cast<const ull*>(wr1 + 0);
            ull wB1 = *reinterpret_cast<const ull*>(wr1 + 2);
            ull wB2 = *reinterpret_cast<const ull*>(wr1 + 4);
            ull wB3 = *reinterpret_cast<const ull*>(wr1 + 6);
            ull wB4 = *reinterpret_cast<const ull*>(wr1 + 8);
            #pragma unroll
            for (int j = 0; j < 4; ++j) {
                float2 ap = *reinterpret_cast<const float2*>(hbase + j * HSS + d);
                ull aX = pack2(ap.x);
                ull aY = pack2(ap.y);
                ffma2(acc[j][0], aX, wA0);
                ffma2(acc[j][1], aX, wA1);
                ffma2(acc[j][2], aX, wA2);
                ffma2(acc[j][3], aX, wA3);
                ffma2(acc[j][4], aX, wA4);
                ffma2(acc[j][0], aY, wB0);
                ffma2(acc[j][1], aY, wB1);
                ffma2(acc[j][2], aY, wB2);
                ffma2(acc[j][3], aY, wB3);
                ffma2(acc[j][4], aY, wB4);
            }
        }
        // in-place write-back (rows half-warp private; reads above precede
        // these stores in warp program order)
        #pragma unroll
        for (int j = 0; j < 4; ++j) {
            float* hrow = H + (vb + j) * HSS + eb;
            #pragma unroll
            for (int k = 0; k < 5; ++k) {
                float2 f = *reinterpret_cast<float2*>(&acc[j][k]);
                f.x = fmaxf(f.x, 0.f);
                f.y = fmaxf(f.y, 0.f);
                *reinterpret_cast<float2*>(hrow + 2*k) = f;
            }
        }
        __syncthreads();                 // all WT/H reads done
        if (layer < 5) {
            const float4* Wl4 = reinterpret_cast<const float4*>(W + (size_t)(layer+1) * WSIZE);
            for (int idx = tid; idx < WSIZE / 4; idx += 512) {
                float4 v = Wl4[idx];
                int e = (idx * 4) / 160, d = (idx * 4) % 160;
                WT[(d+0)*WS + e] = v.x; WT[(d+1)*WS + e] = v.y;
                WT[(d+2)*WS + e] = v.z; WT[(d+3)*WS + e] = v.w;
            }
            __syncthreads();             // next WT staged
        }
    }

    // ---- layer 6: only RESULT(=2) output row needed -> dot + scatter ----
    if (tid < NV) {
        float acc = bias[6 * GE + 2];
        const float* hr = H + tid * HSS;
        #pragma unroll 8
        for (int d = 0; d < GE; ++d) acc = fmaf(hr[d], w6[d], acc);
        int tok = sTok[tid >> 1];
        if (tok >= 0) {
            float r = rintf(acc);                     // round-half-even
            r = fminf(fmaxf(r, 0.f), 15.f);
            int off = ((tid & 1) ? 144 : 128) + (int)r;
            float* p = out + (size_t)tok * 512 + off;
            *p += 2.0f;                                // unique (tok,slot)
        }
    }
}

extern "C" void kernel_launch(void* const* d_in, const int* in_sizes, int n_in,
                              void* d_out, int out_size) {
    const float* x = (const float*)d_in[0];
    const float* W = (const float*)d_in[1];
    const float* b = (const float*)d_in[2];
    float* out = (float*)d_out;

    int ntok = in_sizes[0] / 512;
    if (ntok > MAX_NTOK) ntok = MAX_NTOK;

    static float* count_ptr = nullptr;
    if (!count_ptr) cudaGetSymbolAddress((void**)&count_ptr, g_count);

    cudaFuncSetAttribute(mlp_kernel,
                         cudaFuncAttributeMaxDynamicSharedMemorySize, SMEM_BYTES);

    cudaMemsetAsync(count_ptr, 0, sizeof(int));
    int cd_blocks = (ntok + 7) / 8;
    copy_detect_kernel<<<cd_blocks, 256>>>(x, out, ntok);
    int mlp_blocks = (ntok + TOKB - 1) / TOKB;
    mlp_kernel<<<mlp_blocks, 512, SMEM_BYTES>>>(W, b, out);
}

// round 14
// speedup vs baseline: 1.0018x; 1.0018x over previous
#include <cuda_runtime.h>
#include <cstdint>

typedef unsigned long long ull;

#define MAX_NTOK 32768
#define GE 160
#define WSIZE (160*160)
#define TOKB 64
#define NV 128            // GE-vectors per block (2 per token)
#define HSS 160           // H row stride (floats), even -> 8B aligned rows
#define WS  162           // transposed-W row stride (floats), even for LDS.64
#define SMEM_FLOATS (GE*WS + NV*HSS + GE)
#define SMEM_BYTES  (SMEM_FLOATS*4)      // 186 368 B

__device__ int   g_count;
__device__ int   g_tok[MAX_NTOK];
__device__ int   g_nib[MAX_NTOK];
__device__ float g_op [MAX_NTOK];

// ---- packed fp32x2 helpers (Blackwell FFMA2 path) ----
__device__ __forceinline__ void ffma2(ull& d, ull a, ull b) {
    asm("fma.rn.f32x2 %0, %1, %2, %0;" : "+l"(d) : "l"(a), "l"(b));
}
__device__ __forceinline__ ull pack2(float x) {
    ull r;
    asm("mov.b64 %0, {%1, %1};" : "=l"(r) : "f"(x));
    return r;
}

// first index k in [0,16) of the 16-float window whose value > 0.5, else 0.
__device__ __forceinline__ int first_set_idx(unsigned b0, unsigned b1,
                                             unsigned b2, unsigned b3, int sh) {
    int best = 100;
    unsigned m;
    m = (b0 >> sh) & 0xFu; if (m) { int c = 4*(__ffs(m)-1) + 0; if (c < best) best = c; }
    m = (b1 >> sh) & 0xFu; if (m) { int c = 4*(__ffs(m)-1) + 1; if (c < best) best = c; }
    m = (b2 >> sh) & 0xFu; if (m) { int c = 4*(__ffs(m)-1) + 2; if (c < best) best = c; }
    m = (b3 >> sh) & 0xFu; if (m) { int c = 4*(__ffs(m)-1) + 3; if (c < best) best = c; }
    return (best >= 100) ? 0 : best;
}

// One warp per token: float4 copy in->out; decode gates/nibbles/opcode from the
// already-loaded registers via ballots; append active tokens to compaction list.
__global__ void __launch_bounds__(256)
copy_detect_kernel(const float* __restrict__ x, float* __restrict__ out, int ntok) {
    int tok  = blockIdx.x * 8 + (threadIdx.x >> 5);
    int lane = threadIdx.x & 31;
    if (tok >= ntok) return;

    const float4* src = reinterpret_cast<const float4*>(x) + (size_t)tok * 128;
    float4*       dst = reinterpret_cast<float4*>(out)      + (size_t)tok * 128;

    float4 v0 = src[lane];
    float4 v1 = src[lane + 32];
    float4 v2 = src[lane + 64];
    float4 v3 = src[lane + 96];
    dst[lane]      = v0;
    dst[lane + 32] = v1;
    dst[lane + 64] = v2;
    dst[lane + 96] = v3;

    unsigned b0 = __ballot_sync(0xffffffffu, v0.x > 0.5f);
    unsigned b1 = __ballot_sync(0xffffffffu, v0.y > 0.5f);
    unsigned b2 = __ballot_sync(0xffffffffu, v0.z > 0.5f);
    unsigned b3 = __ballot_sync(0xffffffffu, v0.w > 0.5f);

    float op = __shfl_sync(0xffffffffu, v0.y, 7);   // float 29 = OPCODE_BASE+27

    if (lane == 0 && v0.x >= 0.5f && v0.y >= 0.5f) {
        int a_lo = first_set_idx(b0, b1, b2, b3, 16);
        int a_hi = first_set_idx(b0, b1, b2, b3, 20);
        int b_lo = first_set_idx(b0, b1, b2, b3, 24);
        int b_hi = first_set_idx(b0, b1, b2, b3, 28);
        int idx = atomicAdd(&g_count, 1);
        g_tok[idx] = tok;
        g_nib[idx] = a_lo | (a_hi << 8) | (b_lo << 16) | (b_hi << 24);
        g_op[idx]  = op;
    }
}

// 64 active tokens (128 GE-vectors) per block, 512 threads (16 warps).
// Thread (vg,eg): vg=tid>>4 (half-warp) owns 4 vectors, eg=tid&15 owns 10 outputs.
// H rows half-warp-private -> single in-place H buffer, no intra-layer syncs.
__global__ void __launch_bounds__(512, 1)
mlp_kernel(const float* __restrict__ W, const float* __restrict__ bias,
           float* __restrict__ out) {
    extern __shared__ float smf[];
    float* WT = smf;                  // [160][WS] transposed layer weights
    float* H  = smf + GE * WS;        // [NV][HSS]
    float* w6 = H + NV * HSS;         // [160]
    __shared__ float sA[NV], sBn[NV], sOp[NV];
    __shared__ int   sTok[TOKB];

    int count = g_count;
    int t0 = blockIdx.x * TOKB;
    if (t0 >= count) return;
    int tid = threadIdx.x;

    // ---- prologue: token metadata, stage WT(layer1) and w6 ----
    if (tid < TOKB) {
        int gi = t0 + tid;
        if (gi < count) {
            int   nib = g_nib[gi];
            float op  = g_op[gi];
            sTok[tid]    = g_tok[gi];
            sA [2*tid]   = (float)( nib        & 0xFF);
            sA [2*tid+1] = (float)((nib >> 8)  & 0xFF);
            sBn[2*tid]   = (float)((nib >> 16) & 0xFF);
            sBn[2*tid+1] = (float)((nib >> 24) & 0xFF);
            sOp[2*tid]   = op;
            sOp[2*tid+1] = op;
        } else {
            sTok[tid] = -1;
            sA [2*tid] = 0.f; sA [2*tid+1] = 0.f;
            sBn[2*tid] = 0.f; sBn[2*tid+1] = 0.f;
            sOp[2*tid] = 0.f; sOp[2*tid+1] = 0.f;
        }
    }
    {
        const float4* Wl4 = reinterpret_cast<const float4*>(W + WSIZE);
        for (int idx = tid; idx < WSIZE / 4; idx += 512) {
            float4 v = Wl4[idx];
            int e = (idx * 4) / 160, d = (idx * 4) % 160;   // 4 consecutive d
            WT[(d+0)*WS + e] = v.x; WT[(d+1)*WS + e] = v.y;
            WT[(d+2)*WS + e] = v.z; WT[(d+3)*WS + e] = v.w;
        }
        if (tid < GE) w6[tid] = W[6*WSIZE + 2*GE + tid];
    }
    __syncthreads();

    int vg = tid >> 4, eg = tid & 15;   // vg: half-warp id (0..31)
    int vb = vg * 4,   eb = eg * 10;

    // ---- layer 0: input is 3-sparse (NIB_A@0, NIB_B@1, op@30) ----
    {
        float wc0[10], wc1[10], wc30[10], bb[10];
        #pragma unroll
        for (int k = 0; k < 10; ++k) {
            int e = eb + k;
            wc0[k]  = W[e*160 + 0];
            wc1[k]  = W[e*160 + 1];
            wc30[k] = W[e*160 + 30];
            bb[k]   = bias[e];
        }
        #pragma unroll
        for (int j = 0; j < 4; ++j) {
            int v = vb + j;
            float a = sA[v], bn = sBn[v], op = sOp[v];
            float* hrow = H + v * HSS;
            #pragma unroll
            for (int k = 0; k < 10; ++k) {
                float acc = bb[k];
                acc = fmaf(a,  wc0[k],  acc);
                acc = fmaf(bn, wc1[k],  acc);
                acc = fmaf(op, wc30[k], acc);
                hrow[eb + k] = fmaxf(acc, 0.f);
            }
        }
    }
    // H rows are half-warp private; same warp reads them next -> no sync needed.

    // ---- dense layers 1..5: FFMA2, d-unrolled x2, in-place H ----
    for (int layer = 1; layer <= 5; ++layer) {
        const float* bl = bias + layer * GE + eb;
        ull acc[4][5];
        #pragma unroll
        for (int k = 0; k < 5; ++k) {
            ull bv = *reinterpret_cast<const ull*>(bl + 2*k);
            acc[0][k] = bv; acc[1][k] = bv; acc[2][k] = bv; acc[3][k] = bv;
        }
        const float* hbase = H + vb * HSS;
        const float* wp = WT + eb;
        #pragma unroll 2
        for (int d = 0; d < GE; d += 2) {
            const float* wr0 = wp + d * WS;
            const float* wr1 = wr0 + WS;
            ull wA0 = *reinterpret_cast<const ull*>(wr0 + 0);
            ull wA1 = *reinterpret_cast<const ull*>(wr0 + 2);
            ull wA2 = *reinterpret_cast<const ull*>(wr0 + 4);
            ull wA3 = *reinterpret_cast<const ull*>(wr0 + 6);
            ull wA4 = *reinterpret_cast<const ull*>(wr0 + 8);
            ull wB0 = *reinterpret_cast<const ull*>(wr1 + 0);
            ull wB1 = *reinterpret_cast<const ull*>(wr1 + 2);
            ull wB2 = *reinterpret_cast<const ull*>(wr1 + 4);
            ull wB3 = *reinterpret_cast<const ull*>(wr1 + 6);
            ull wB4 = *reinterpret_cast<const ull*>(wr1 + 8);
            #pragma unroll
            for (int j = 0; j < 4; ++j) {
                float2 ap = *reinterpret_cast<const float2*>(hbase + j * HSS + d);
                ull aX = pack2(ap.x);
                ull aY = pack2(ap.y);
                ffma2(acc[j][0], aX, wA0);
                ffma2(acc[j][1], aX, wA1);
                ffma2(acc[j][2], aX, wA2);
                ffma2(acc[j][3], aX, wA3);
                ffma2(acc[j][4], aX, wA4);
                ffma2(acc[j][0], aY, wB0);
                ffma2(acc[j][1], aY, wB1);
                ffma2(acc[j][2], aY, wB2);
                ffma2(acc[j][3], aY, wB3);
                ffma2(acc[j][4], aY, wB4);
            }
        }
        // in-place write-back (rows half-warp private; reads above precede
        // these stores in warp program order)
        #pragma unroll
        for (int j = 0; j < 4; ++j) {
            float* hrow = H + (vb + j) * HSS + eb;
            #pragma unroll
            for (int k = 0; k < 5; ++k) {
                float2 f = *reinterpret_cast<float2*>(&acc[j][k]);
                f.x = fmaxf(f.x, 0.f);
                f.y = fmaxf(f.y, 0.f);
                *reinterpret_cast<float2*>(hrow + 2*k) = f;
            }
        }
        __syncthreads();                 // all WT/H reads done
        if (layer < 5) {
            const float4* Wl4 = reinterpret_cast<const float4*>(W + (size_t)(layer+1) * WSIZE);
            for (int idx = tid; idx < WSIZE / 4; idx += 512) {
                float4 v = Wl4[idx];
                int e = (idx * 4) / 160, d = (idx * 4) % 160;
                WT[(d+0)*WS + e] = v.x; WT[(d+1)*WS + e] = v.y;
                WT[(d+2)*WS + e] = v.z; WT[(d+3)*WS + e] = v.w;
            }
            __syncthreads();             // next WT staged
        }
    }

    // ---- layer 6: only RESULT(=2) output row needed -> dot + scatter ----
    if (tid < NV) {
        float acc = bias[6 * GE + 2];
        const float* hr = H + tid * HSS;
        #pragma unroll 8
        for (int d = 0; d < GE; ++d) acc = fmaf(hr[d], w6[d], acc);
        int tok = sTok[tid >> 1];
        if (tok >= 0) {
            float r = rintf(acc);                     // round-half-even
            r = fminf(fmaxf(r, 0.f), 15.f);
            int off = ((tid & 1) ? 144 : 128) + (int)r;
            float* p = out + (size_t)tok * 512 + off;
            *p += 2.0f;                                // unique (tok,slot)
        }
    }
}

extern "C" void kernel_launch(void* const* d_in, const int* in_sizes, int n_in,
                              void* d_out, int out_size) {
    const float* x = (const float*)d_in[0];
    const float* W = (const float*)d_in[1];
    const float* b = (const float*)d_in[2];
    float* out = (float*)d_out;

    int ntok = in_sizes[0] / 512;
    if (ntok > MAX_NTOK) ntok = MAX_NTOK;

    static float* count_ptr = nullptr;
    if (!count_ptr) cudaGetSymbolAddress((void**)&count_ptr, g_count);

    cudaFuncSetAttribute(mlp_kernel,
                         cudaFuncAttributeMaxDynamicSharedMemorySize, SMEM_BYTES);

    cudaMemsetAsync(count_ptr, 0, sizeof(int));
    int cd_blocks = (ntok + 7) / 8;
    copy_detect_kernel<<<cd_blocks, 256>>>(x, out, ntok);
    int mlp_blocks = (ntok + TOKB - 1) / TOKB;
    mlp_kernel<<<mlp_blocks, 512, SMEM_BYTES>>>(W, b, out);
}

// round 16
// speedup vs baseline: 1.0457x; 1.0437x over previous
#include <cuda_runtime.h>
#include <cstdint>

typedef unsigned long long ull;

#define MAX_NTOK 32768
#define GE 160
#define WSIZE (160*160)
#define TOKB 64
#define NV 128            // GE-vectors per block (2 per token)
#define HSS 160           // H row stride (floats), even -> 8B aligned rows
#define WS  162           // transposed-W row stride (floats), even for LDS.64
#define SMEM_FLOATS (GE*WS + NV*HSS + GE)
#define SMEM_BYTES  (SMEM_FLOATS*4)      // 186 368 B

__device__ int   g_count;
__device__ int   g_tok[MAX_NTOK];
__device__ int   g_nib[MAX_NTOK];
__device__ float g_op [MAX_NTOK];

// ---- packed fp32x2 helpers (Blackwell FFMA2 path) ----
__device__ __forceinline__ void ffma2(ull& d, ull a, ull b) {
    asm("fma.rn.f32x2 %0, %1, %2, %0;" : "+l"(d) : "l"(a), "l"(b));
}
__device__ __forceinline__ ull pack2(float x) {
    ull r;
    asm("mov.b64 %0, {%1, %1};" : "=l"(r) : "f"(x));
    return r;
}

// first index k in [0,16) of the 16-float window whose value > 0.5, else 0.
__device__ __forceinline__ int first_set_idx(unsigned b0, unsigned b1,
                                             unsigned b2, unsigned b3, int sh) {
    int best = 100;
    unsigned m;
    m = (b0 >> sh) & 0xFu; if (m) { int c = 4*(__ffs(m)-1) + 0; if (c < best) best = c; }
    m = (b1 >> sh) & 0xFu; if (m) { int c = 4*(__ffs(m)-1) + 1; if (c < best) best = c; }
    m = (b2 >> sh) & 0xFu; if (m) { int c = 4*(__ffs(m)-1) + 2; if (c < best) best = c; }
    m = (b3 >> sh) & 0xFu; if (m) { int c = 4*(__ffs(m)-1) + 3; if (c < best) best = c; }
    return (best >= 100) ? 0 : best;
}

// One warp per token: float4 copy in->out; decode gates/nibbles/opcode from the
// already-loaded registers via ballots; append active tokens to compaction list.
__global__ void __launch_bounds__(256)
copy_detect_kernel(const float* __restrict__ x, float* __restrict__ out, int ntok) {
    int tok  = blockIdx.x * 8 + (threadIdx.x >> 5);
    int lane = threadIdx.x & 31;
    if (tok >= ntok) return;

    const float4* src = reinterpret_cast<const float4*>(x) + (size_t)tok * 128;
    float4*       dst = reinterpret_cast<float4*>(out)      + (size_t)tok * 128;

    float4 v0 = src[lane];
    float4 v1 = src[lane + 32];
    float4 v2 = src[lane + 64];
    float4 v3 = src[lane + 96];
    dst[lane]      = v0;
    dst[lane + 32] = v1;
    dst[lane + 64] = v2;
    dst[lane + 96] = v3;

    unsigned b0 = __ballot_sync(0xffffffffu, v0.x > 0.5f);
    unsigned b1 = __ballot_sync(0xffffffffu, v0.y > 0.5f);
    unsigned b2 = __ballot_sync(0xffffffffu, v0.z > 0.5f);
    unsigned b3 = __ballot_sync(0xffffffffu, v0.w > 0.5f);

    float op = __shfl_sync(0xffffffffu, v0.y, 7);   // float 29 = OPCODE_BASE+27

    if (lane == 0 && v0.x >= 0.5f && v0.y >= 0.5f) {
        int a_lo = first_set_idx(b0, b1, b2, b3, 16);
        int a_hi = first_set_idx(b0, b1, b2, b3, 20);
        int b_lo = first_set_idx(b0, b1, b2, b3, 24);
        int b_hi = first_set_idx(b0, b1, b2, b3, 28);
        int idx = atomicAdd(&g_count, 1);
        g_tok[idx] = tok;
        g_nib[idx] = a_lo | (a_hi << 8) | (b_lo << 16) | (b_hi << 24);
        g_op[idx]  = op;
    }
}

// 64 active tokens (128 GE-vectors) per block, 256 threads (8 warps).
// Thread (vg,eg): vg=tid>>4 (half-warp) owns 8 vectors, eg=tid&15 owns 10 outputs.
// Weight LDS amortized over 8 vectors -> 18 LDS.64 per 80 FFMA2.
__global__ void __launch_bounds__(256, 1)
mlp_kernel(const float* __restrict__ W, const float* __restrict__ bias,
           float* __restrict__ out) {
    extern __shared__ float smf[];
    float* WT = smf;                  // [160][WS] transposed layer weights
    float* H  = smf + GE * WS;        // [NV][HSS]
    float* w6 = H + NV * HSS;         // [160]
    __shared__ float sA[NV], sBn[NV], sOp[NV];
    __shared__ int   sTok[TOKB];

    int count = g_count;
    int t0 = blockIdx.x * TOKB;
    if (t0 >= count) return;
    int tid = threadIdx.x;

    // ---- prologue: token metadata, stage WT(layer1) and w6 ----
    if (tid < TOKB) {
        int gi = t0 + tid;
        if (gi < count) {
            int   nib = g_nib[gi];
            float op  = g_op[gi];
            sTok[tid]    = g_tok[gi];
            sA [2*tid]   = (float)( nib        & 0xFF);
            sA [2*tid+1] = (float)((nib >> 8)  & 0xFF);
            sBn[2*tid]   = (float)((nib >> 16) & 0xFF);
            sBn[2*tid+1] = (float)((nib >> 24) & 0xFF);
            sOp[2*tid]   = op;
            sOp[2*tid+1] = op;
        } else {
            sTok[tid] = -1;
            sA [2*tid] = 0.f; sA [2*tid+1] = 0.f;
            sBn[2*tid] = 0.f; sBn[2*tid+1] = 0.f;
            sOp[2*tid] = 0.f; sOp[2*tid+1] = 0.f;
        }
    }
    {
        const float4* Wl4 = reinterpret_cast<const float4*>(W + WSIZE);
        for (int idx = tid; idx < WSIZE / 4; idx += 256) {
            float4 v = Wl4[idx];
            int e = (idx * 4) / 160, d = (idx * 4) % 160;   // 4 consecutive d
            WT[(d+0)*WS + e] = v.x; WT[(d+1)*WS + e] = v.y;
            WT[(d+2)*WS + e] = v.z; WT[(d+3)*WS + e] = v.w;
        }
        if (tid < GE) w6[tid] = W[6*WSIZE + 2*GE + tid];
    }
    __syncthreads();

    int vg = tid >> 4, eg = tid & 15;   // vg: half-warp id (0..15)
    int vb = vg * 8,   eb = eg * 10;

    // ---- layer 0: input is 3-sparse (NIB_A@0, NIB_B@1, op@30) ----
    {
        float wc0[10], wc1[10], wc30[10], bb[10];
        #pragma unroll
        for (int k = 0; k < 10; ++k) {
            int e = eb + k;
            wc0[k]  = W[e*160 + 0];
            wc1[k]  = W[e*160 + 1];
            wc30[k] = W[e*160 + 30];
            bb[k]   = bias[e];
        }
        #pragma unroll
        for (int j = 0; j < 8; ++j) {
            int v = vb + j;
            float a = sA[v], bn = sBn[v], op = sOp[v];
            float* hrow = H + v * HSS;
            #pragma unroll
            for (int k = 0; k < 10; ++k) {
                float acc = bb[k];
                acc = fmaf(a,  wc0[k],  acc);
                acc = fmaf(bn, wc1[k],  acc);
                acc = fmaf(op, wc30[k], acc);
                hrow[eb + k] = fmaxf(acc, 0.f);
            }
        }
    }
    __syncwarp();   // H rows half-warp private; order layer-0 stores vs layer-1 loads

    // ---- dense layers 1..5: FFMA2, j=8, d-unrolled x2, in-place H ----
    for (int layer = 1; layer <= 5; ++layer) {
        const float* bl = bias + layer * GE + eb;
        ull acc[8][5];
        #pragma unroll
        for (int k = 0; k < 5; ++k) {
            ull bv = *reinterpret_cast<const ull*>(bl + 2*k);
            #pragma unroll
            for (int j = 0; j < 8; ++j) acc[j][k] = bv;
        }
        const float* hbase = H + vb * HSS;
        const float* wp = WT + eb;
        #pragma unroll 2
        for (int d = 0; d < GE; d += 2) {
            const float* wr0 = wp + d * WS;
            const float* wr1 = wr0 + WS;
            ull wA0 = *reinterpret_cast<const ull*>(wr0 + 0);
            ull wA1 = *reinterpret_cast<const ull*>(wr0 + 2);
            ull wA2 = *reinterpret_cast<const ull*>(wr0 + 4);
            ull wA3 = *reinterpret_cast<const ull*>(wr0 + 6);
            ull wA4 = *reinterpret_cast<const ull*>(wr0 + 8);
            ull wB0 = *reinterpret_cast<const ull*>(wr1 + 0);
            ull wB1 = *reinterpret_cast<const ull*>(wr1 + 2);
            ull wB2 = *reinterpret_cast<const ull*>(wr1 + 4);
            ull wB3 = *reinterpret_cast<const ull*>(wr1 + 6);
            ull wB4 = *reinterpret_cast<const ull*>(wr1 + 8);
            #pragma unroll
            for (int j = 0; j < 8; ++j) {
                float2 ap = *reinterpret_cast<const float2*>(hbase + j * HSS + d);
                ull aX = pack2(ap.x);
                ull aY = pack2(ap.y);
                ffma2(acc[j][0], aX, wA0);
                ffma2(acc[j][1], aX, wA1);
                ffma2(acc[j][2], aX, wA2);
                ffma2(acc[j][3], aX, wA3);
                ffma2(acc[j][4], aX, wA4);
                ffma2(acc[j][0], aY, wB0);
                ffma2(acc[j][1], aY, wB1);
                ffma2(acc[j][2], aY, wB2);
                ffma2(acc[j][3], aY, wB3);
                ffma2(acc[j][4], aY, wB4);
            }
        }
        // in-place write-back (rows half-warp private; warp is convergent so
        // all lanes' reads above precede these stores)
        #pragma unroll
        for (int j = 0; j < 8; ++j) {
            float* hrow = H + (vb + j) * HSS + eb;
            #pragma unroll
            for (int k = 0; k < 5; ++k) {
                float2 f = *reinterpret_cast<float2*>(&acc[j][k]);
                f.x = fmaxf(f.x, 0.f);
                f.y = fmaxf(f.y, 0.f);
                *reinterpret_cast<float2*>(hrow + 2*k) = f;
            }
        }
        __syncthreads();                 // all WT/H reads done
        if (layer < 5) {
            const float4* Wl4 = reinterpret_cast<const float4*>(W + (size_t)(layer+1) * WSIZE);
            for (int idx = tid; idx < WSIZE / 4; idx += 256) {
                float4 v = Wl4[idx];
                int e = (idx * 4) / 160, d = (idx * 4) % 160;
                WT[(d+0)*WS + e] = v.x; WT[(d+1)*WS + e] = v.y;
                WT[(d+2)*WS + e] = v.z; WT[(d+3)*WS + e] = v.w;
            }
            __syncthreads();             // next WT staged
        }
    }

    // ---- layer 6: only RESULT(=2) output row needed -> dot + scatter ----
    if (tid < NV) {
        float acc = bias[6 * GE + 2];
        const float* hr = H + tid * HSS;
        #pragma unroll 8
        for (int d = 0; d < GE; ++d) acc = fmaf(hr[d], w6[d], acc);
        int tok = sTok[tid >> 1];
        if (tok >= 0) {
            float r = rintf(acc);                     // round-half-even
            r = fminf(fmaxf(r, 0.f), 15.f);
            int off = ((tid & 1) ? 144 : 128) + (int)r;
            float* p = out + (size_t)tok * 512 + off;
            *p += 2.0f;                                // unique (tok,slot)
        }
    }
}

extern "C" void kernel_launch(void* const* d_in, const int* in_sizes, int n_in,
                              void* d_out, int out_size) {
    const float* x = (const float*)d_in[0];
    const float* W = (const float*)d_in[1];
    const float* b = (const float*)d_in[2];
    float* out = (float*)d_out;

    int ntok = in_sizes[0] / 512;
    if (ntok > MAX_NTOK) ntok = MAX_NTOK;

    static float* count_ptr = nullptr;
    if (!count_ptr) cudaGetSymbolAddress((void**)&count_ptr, g_count);

    cudaFuncSetAttribute(mlp_kernel,
                         cudaFuncAttributeMaxDynamicSharedMemorySize, SMEM_BYTES);

    cudaMemsetAsync(count_ptr, 0, sizeof(int));
    int cd_blocks = (ntok + 7) / 8;
    copy_detect_kernel<<<cd_blocks, 256>>>(x, out, ntok);
    int mlp_blocks = (ntok + TOKB - 1) / TOKB;
    mlp_kernel<<<mlp_blocks, 256, SMEM_BYTES>>>(W, b, out);
}